// round 12
// baseline (speedup 1.0000x reference)
#include <cuda_runtime.h>
#include <cuda_bf16.h>
#include <cstdint>

#define D_IN   64
#define D_OUT  64
#define D_HID  128
#define MAX_NODES 100000
#define NPB    256                 // nodes per CTA (2 M-tiles of 128)
#define NT     256                 // threads per block (8 warps x 16 rows/tile)
#define PREP_BLOCKS 65
#define EPT    16

// Scratch. g_deg: consume-reset invariant (zero at load, reset after read).
__device__ int   g_deg[MAX_NODES];
__device__ float g_bW[D_OUT];
// W12^T row-major [c][k], bf16 hi/lo (k contiguous).
__device__ __align__(16) unsigned short g_WT_h[D_OUT * D_IN];
__device__ __align__(16) unsigned short g_WT_l[D_OUT * D_IN];

// ---------------------------------------------------------------------------
__device__ __forceinline__ void mma_bf16(float& d0, float& d1, float& d2, float& d3,
                                         uint32_t a0, uint32_t a1, uint32_t a2, uint32_t a3,
                                         uint32_t b0, uint32_t b1) {
    asm volatile(
        "mma.sync.aligned.m16n8k16.row.col.f32.bf16.bf16.f32 "
        "{%0,%1,%2,%3}, {%4,%5,%6,%7}, {%8,%9}, {%0,%1,%2,%3};"
        : "+f"(d0), "+f"(d1), "+f"(d2), "+f"(d3)
        : "r"(a0), "r"(a1), "r"(a2), "r"(a3), "r"(b0), "r"(b1));
}

// Split a float2 into packed bf16x2 hi + lo (residual) fragments.
__device__ __forceinline__ void split2(float2 f, uint32_t& hi, uint32_t& lo) {
    __nv_bfloat162 h = __float22bfloat162_rn(f);
    float2 r;
    r.x = f.x - __bfloat162float(__low2bfloat16(h));
    r.y = f.y - __bfloat162float(__high2bfloat16(h));
    __nv_bfloat162 l = __float22bfloat162_rn(r);
    hi = *reinterpret_cast<uint32_t*>(&h);
    lo = *reinterpret_cast<uint32_t*>(&l);
}

// ---------------------------------------------------------------------------
// K1: blocks [0,65) -> W12^T hi/lo bf16 + bW. Rest: degree histogram.
__global__ __launch_bounds__(256) void prep_hist_kernel(
    const int* __restrict__ ei32,
    const float* __restrict__ W1,
    const float* __restrict__ b1,
    const float* __restrict__ W2,
    int E)
{
    const int tid = threadIdx.x;

    if (blockIdx.x < PREP_BLOCKS) {
        const int r  = blockIdx.x;       // k index (or 64 => bW)
        const int j  = tid & 63;         // output column c
        const int kc = tid >> 6;
        const float* src = (r < D_IN) ? (W1 + (size_t)r * D_HID) : b1;

        float a = 0.f;
        #pragma unroll 8
        for (int k = kc * 32; k < kc * 32 + 32; ++k)
            a = fmaf(src[k], W2[(size_t)k * D_OUT + j], a);

        __shared__ float red[4][64];
        red[kc][j] = a;
        __syncthreads();
        if (kc == 0) {
            float v = red[0][j] + red[1][j] + red[2][j] + red[3][j];
            if (r < D_IN) {
                __nv_bfloat16 h = __float2bfloat16_rn(v);
                __nv_bfloat16 l = __float2bfloat16_rn(v - __bfloat162float(h));
                g_WT_h[j * D_IN + r] = *reinterpret_cast<unsigned short*>(&h);
                g_WT_l[j * D_IN + r] = *reinterpret_cast<unsigned short*>(&l);
            } else {
                g_bW[j] = v;
            }
        }
        return;
    }

    // ---- histogram over edge_index[1] (dst row), dtype self-detecting ----
    __shared__ int s_is64;
    if (tid == 0) {
        int is64 = 1;
        #pragma unroll
        for (int i = 1; i < 64; i += 2)
            if (ei32[i] != 0) is64 = 0;
        s_is64 = is64;
    }
    __syncthreads();

    const int hb = blockIdx.x - PREP_BLOCKS;
    const long long i0 = ((long long)hb * 256 + tid) * EPT;
    if (i0 >= E) return;

    if (s_is64) {
        const unsigned long long* p = (const unsigned long long*)ei32 + E;
        if (i0 + EPT <= E) {
            const ulonglong2* q = (const ulonglong2*)(p + i0);
            #pragma unroll
            for (int c = 0; c < EPT / 2; ++c) {
                ulonglong2 v = q[c];
                atomicAdd(&g_deg[(int)v.x], 1);
                atomicAdd(&g_deg[(int)v.y], 1);
            }
        } else {
            for (long long j = i0; j < E; ++j) atomicAdd(&g_deg[(int)p[j]], 1);
        }
    } else {
        const int* p = (const int*)ei32 + E;
        if (i0 + EPT <= E) {
            const int4* q = (const int4*)(p + i0);
            #pragma unroll
            for (int c = 0; c < EPT / 4; ++c) {
                int4 v = q[c];
                atomicAdd(&g_deg[v.x], 1); atomicAdd(&g_deg[v.y], 1);
                atomicAdd(&g_deg[v.z], 1); atomicAdd(&g_deg[v.w], 1);
            }
        } else {
            for (long long j = i0; j < E; ++j) atomicAdd(&g_deg[p[j]], 1);
        }
    }
}

// ---------------------------------------------------------------------------
// SMEM byte offsets (dynamic) — W tile + biases + 256 scales (no x tile).
#define SM_SC  0                              // 256 f32 scales (1+deg)
#define SM_BW  1024                           // 64 f32
#define SM_B2  1280                           // 64 f32
#define SM_WH  1536                           // 64 x 144B
#define SM_WL  (SM_WH + 64 * 144)             // 64 x 144B
#define SM_TOTAL (SM_WL + 64 * 144)           // 19968 B

// K2 (HMMA): per CTA, TWO sequential 128-node tiles sharing one W stage.
// D = xh@Wh + xh@Wl + xl@Wh (fp32 acc); out[n] = (1+deg)*(D[n]+bW)+b2.
// A fragments load directly from global; no barrier between tiles.
__global__ __launch_bounds__(NT, 3) void gnn_mma_kernel(
    const float* __restrict__ x,
    const float* __restrict__ b2,
    float* __restrict__ out,
    int n)
{
    extern __shared__ char smem[];
    const int tid = threadIdx.x;
    const int wid = tid >> 5;
    const int lid = tid & 31;
    const int g   = lid >> 2;                  // 0..7
    const int t   = lid & 3;                   // 0..3
    const int base = blockIdx.x * NPB;

    // Degree read + consume-reset + scale into smem (both tiles, pre-barrier)
    {
        const int node = base + tid;
        int d = 0;
        if (node < n) { d = g_deg[node]; g_deg[node] = 0; }
        ((float*)(smem + SM_SC))[tid] = 1.0f + (float)d;
    }
    if (tid < D_OUT) {
        ((float*)(smem + SM_BW))[tid] = g_bW[tid];
        ((float*)(smem + SM_B2))[tid] = b2[tid];
    }

    // Stage W^T hi/lo once: 64 rows x 64 bf16 (=16 uint2/row) -> padded rows
    #pragma unroll
    for (int it = 0; it < 4; ++it) {
        const int u = it * NT + tid;           // 0..1023
        const int c = u >> 4, q = u & 15;
        *(uint2*)(smem + SM_WH + c * 144 + q * 8) =
            *(const uint2*)((const char*)g_WT_h + c * 128 + q * 8);
        *(uint2*)(smem + SM_WL + c * 144 + q * 8) =
            *(const uint2*)((const char*)g_WT_l + c * 128 + q * 8);
    }
    __syncthreads();                           // the ONLY block barrier

    const float* sc = (const float*)(smem + SM_SC);
    const float* bw = (const float*)(smem + SM_BW);
    const float* bb = (const float*)(smem + SM_B2);
    const uint32_t boff = (uint32_t)(g * 144 + 4 * t);

    #pragma unroll
    for (int tile = 0; tile < 2; ++tile) {
        const int tbase = base + tile * 128;

        float acc[32];                         // 8 n-tiles x {d0,d1,d2,d3}
        #pragma unroll
        for (int i = 0; i < 32; ++i) acc[i] = 0.f;

        const int rowA = tbase + wid * 16 + g; // global node for a0/a2
        const int r0c  = (rowA     < n) ? rowA     : (n - 1);
        const int r1c  = (rowA + 8 < n) ? rowA + 8 : (n - 1);
        const float* xr0 = x + (size_t)r0c * D_IN;
        const float* xr1 = x + (size_t)r1c * D_IN;

        #pragma unroll
        for (int ks = 0; ks < 4; ++ks) {
            const int c0 = ks * 16 + 2 * t;
            const float2 f00 = *(const float2*)(xr0 + c0);       // a0
            const float2 f10 = *(const float2*)(xr1 + c0);       // a1
            const float2 f01 = *(const float2*)(xr0 + c0 + 8);   // a2
            const float2 f11 = *(const float2*)(xr1 + c0 + 8);   // a3

            uint32_t ah0, al0, ah1, al1, ah2, al2, ah3, al3;
            split2(f00, ah0, al0);
            split2(f10, ah1, al1);
            split2(f01, ah2, al2);
            split2(f11, ah3, al3);

            #pragma unroll
            for (int nt = 0; nt < 8; ++nt) {
                const uint32_t bk = boff + nt * 8 * 144 + ks * 32;
                const uint32_t bh0 = *(const uint32_t*)(smem + SM_WH + bk);
                const uint32_t bh1 = *(const uint32_t*)(smem + SM_WH + bk + 16);
                const uint32_t bl0 = *(const uint32_t*)(smem + SM_WL + bk);
                const uint32_t bl1 = *(const uint32_t*)(smem + SM_WL + bk + 16);
                float* a = acc + nt * 4;
                mma_bf16(a[0], a[1], a[2], a[3], ah0, ah1, ah2, ah3, bh0, bh1);
                mma_bf16(a[0], a[1], a[2], a[3], ah0, ah1, ah2, ah3, bl0, bl1);
                mma_bf16(a[0], a[1], a[2], a[3], al0, al1, al2, al3, bh0, bh1);
            }
        }

        // Direct-from-fragment epilogue
        {
            const int r0 = tile * 128 + wid * 16 + g;
            const int node0 = base + r0;
            const int node1 = node0 + 8;
            const bool v0 = (node0 < n);
            const bool v1 = (node1 < n);
            const float s0 = sc[r0];
            const float s1 = sc[r0 + 8];
            float* op0 = out + (size_t)node0 * D_OUT;
            float* op1 = out + (size_t)node1 * D_OUT;

            #pragma unroll
            for (int nt = 0; nt < 8; ++nt) {
                const int c = nt * 8 + 2 * t;
                const float2 bwv = *(const float2*)(bw + c);
                const float2 bbv = *(const float2*)(bb + c);
                const float* a = acc + nt * 4;
                if (v0) {
                    float2 r;
                    r.x = fmaf(s0, a[0] + bwv.x, bbv.x);
                    r.y = fmaf(s0, a[1] + bwv.y, bbv.y);
                    *(float2*)(op0 + c) = r;
                }
                if (v1) {
                    float2 r;
                    r.x = fmaf(s1, a[2] + bwv.x, bbv.x);
                    r.y = fmaf(s1, a[3] + bwv.y, bbv.y);
                    *(float2*)(op1 + c) = r;
                }
            }
        }
    }
}

// ---------------------------------------------------------------------------
extern "C" void kernel_launch(void* const* d_in, const int* in_sizes, int n_in,
                              void* d_out, int out_size) {
    const float* x  = (const float*)d_in[0];
    const void*  ei = d_in[1];
    const float* W1 = (const float*)d_in[2];
    const float* b1 = (const float*)d_in[3];
    const float* W2 = (const float*)d_in[4];
    const float* b2 = (const float*)d_in[5];
    float* out = (float*)d_out;

    const int n = in_sizes[0] / D_IN;   // 100000
    const int E = in_sizes[1] / 2;      // 1000000

    const int hist_blocks = (E + 256 * EPT - 1) / (256 * EPT);
    prep_hist_kernel<<<PREP_BLOCKS + hist_blocks, 256>>>(
        (const int*)ei, W1, b1, W2, E);

    cudaFuncSetAttribute(gnn_mma_kernel,
                         cudaFuncAttributeMaxDynamicSharedMemorySize, SM_TOTAL);
    gnn_mma_kernel<<<(n + NPB - 1) / NPB, NT, SM_TOTAL>>>(x, b2, out, n);
}

// round 13
// speedup vs baseline: 1.0720x; 1.0720x over previous
#include <cuda_runtime.h>
#include <cuda_fp16.h>
#include <cstdint>

#define D_IN   64
#define D_OUT  64
#define D_HID  128
#define MAX_NODES 100000
#define NPB    128                 // nodes per block (M tile)
#define NT     256                 // threads per block (8 warps x 16 rows)
#define PREP_BLOCKS 65
#define EPT    8

// Scratch. g_deg: consume-reset invariant (zero at load, reset after read).
__device__ int   g_deg[MAX_NODES];
__device__ float g_bW[D_OUT];
// W12^T row-major [c][k], fp16 hi/lo (k contiguous).
__device__ __align__(16) unsigned short g_WT_h[D_OUT * D_IN];
__device__ __align__(16) unsigned short g_WT_l[D_OUT * D_IN];

// ---------------------------------------------------------------------------
__device__ __forceinline__ void mma_f16(float& d0, float& d1, float& d2, float& d3,
                                        uint32_t a0, uint32_t a1, uint32_t a2, uint32_t a3,
                                        uint32_t b0, uint32_t b1) {
    asm volatile(
        "mma.sync.aligned.m16n8k16.row.col.f32.f16.f16.f32 "
        "{%0,%1,%2,%3}, {%4,%5,%6,%7}, {%8,%9}, {%0,%1,%2,%3};"
        : "+f"(d0), "+f"(d1), "+f"(d2), "+f"(d3)
        : "r"(a0), "r"(a1), "r"(a2), "r"(a3), "r"(b0), "r"(b1));
}

// ---------------------------------------------------------------------------
// K1: blocks [0,65) -> W12^T hi/lo fp16 + bW. Rest: degree histogram.
__global__ __launch_bounds__(256) void prep_hist_kernel(
    const int* __restrict__ ei32,
    const float* __restrict__ W1,
    const float* __restrict__ b1,
    const float* __restrict__ W2,
    int E)
{
    const int tid = threadIdx.x;

    if (blockIdx.x < PREP_BLOCKS) {
        const int r  = blockIdx.x;       // k index (or 64 => bW)
        const int j  = tid & 63;         // output column c
        const int kc = tid >> 6;
        const float* src = (r < D_IN) ? (W1 + (size_t)r * D_HID) : b1;

        float a = 0.f;
        #pragma unroll 8
        for (int k = kc * 32; k < kc * 32 + 32; ++k)
            a = fmaf(src[k], W2[(size_t)k * D_OUT + j], a);

        __shared__ float red[4][64];
        red[kc][j] = a;
        __syncthreads();
        if (kc == 0) {
            float v = red[0][j] + red[1][j] + red[2][j] + red[3][j];
            if (r < D_IN) {
                __half h = __float2half_rn(v);
                __half l = __float2half_rn(v - __half2float(h));
                g_WT_h[j * D_IN + r] = *reinterpret_cast<unsigned short*>(&h);
                g_WT_l[j * D_IN + r] = *reinterpret_cast<unsigned short*>(&l);
            } else {
                g_bW[j] = v;
            }
        }
        return;
    }

    // ---- histogram over edge_index[1] (dst row), dtype self-detecting ----
    __shared__ int s_is64;
    if (tid == 0) {
        int is64 = 1;
        #pragma unroll
        for (int i = 1; i < 64; i += 2)
            if (ei32[i] != 0) is64 = 0;
        s_is64 = is64;
    }
    __syncthreads();

    const int hb = blockIdx.x - PREP_BLOCKS;
    const long long i0 = ((long long)hb * 256 + tid) * EPT;
    if (i0 >= E) return;

    if (s_is64) {
        const unsigned long long* p = (const unsigned long long*)ei32 + E;
        if (i0 + EPT <= E) {
            const ulonglong2* q = (const ulonglong2*)(p + i0);
            #pragma unroll
            for (int c = 0; c < EPT / 2; ++c) {
                ulonglong2 v = q[c];
                atomicAdd(&g_deg[(int)v.x], 1);
                atomicAdd(&g_deg[(int)v.y], 1);
            }
        } else {
            for (long long j = i0; j < E; ++j) atomicAdd(&g_deg[(int)p[j]], 1);
        }
    } else {
        const int* p = (const int*)ei32 + E;
        if (i0 + EPT <= E) {
            const int4* q = (const int4*)(p + i0);
            #pragma unroll
            for (int c = 0; c < EPT / 4; ++c) {
                int4 v = q[c];
                atomicAdd(&g_deg[v.x], 1); atomicAdd(&g_deg[v.y], 1);
                atomicAdd(&g_deg[v.z], 1); atomicAdd(&g_deg[v.w], 1);
            }
        } else {
            for (long long j = i0; j < E; ++j) atomicAdd(&g_deg[p[j]], 1);
        }
    }
}

// ---------------------------------------------------------------------------
// SMEM byte offsets (dynamic)
#define SM_SC  0                              // 128 f32 scales (1+deg)
#define SM_BW  512                            // 64 f32
#define SM_B2  768                            // 64 f32
#define SM_WH  1024                           // 64 x 144B
#define SM_WL  (SM_WH + 64 * 144)             // 64 x 144B
#define SM_XH  (SM_WL + 64 * 144)             // 128 x 144B (fp16, single)
#define SM_TOTAL (SM_XH + 128 * 144)          // 38656 B

// K2 (HMMA fp16): per block of 128 nodes,
//   D = x_h @ (W_h + W_l)  (x single fp16, W split hi/lo, fp32 acc)
//   out[n] = (1+deg)*(D[n] + bW) + b2 — stored straight from fragments.
__global__ __launch_bounds__(NT, 4) void gnn_mma_kernel(
    const float* __restrict__ x,
    const float* __restrict__ b2,
    float* __restrict__ out,
    int n)
{
    extern __shared__ char smem[];
    const int tid = threadIdx.x;
    const int wid = tid >> 5;
    const int lid = tid & 31;
    const int g   = lid >> 2;                  // 0..7
    const int t   = lid & 3;                   // 0..3
    const int base = blockIdx.x * NPB;

    // Degree read + consume-reset + scale into smem
    if (tid < NPB) {
        const int node = base + tid;
        int d = 0;
        if (node < n) { d = g_deg[node]; g_deg[node] = 0; }
        ((float*)(smem + SM_SC))[tid] = 1.0f + (float)d;
    }
    if (tid < D_OUT) {
        ((float*)(smem + SM_BW))[tid] = g_bW[tid];
        ((float*)(smem + SM_B2))[tid] = b2[tid];
    }

    // Stage W^T hi/lo: 64 rows x 64 fp16 (=16 uint2/row) -> padded rows
    #pragma unroll
    for (int it = 0; it < 4; ++it) {
        const int u = it * NT + tid;           // 0..1023
        const int c = u >> 4, q = u & 15;
        *(uint2*)(smem + SM_WH + c * 144 + q * 8) =
            *(const uint2*)((const char*)g_WT_h + c * 128 + q * 8);
        *(uint2*)(smem + SM_WL + c * 144 + q * 8) =
            *(const uint2*)((const char*)g_WT_l + c * 128 + q * 8);
    }

    // Stage x: f32 -> fp16 (single), padded rows
    #pragma unroll
    for (int it = 0; it < 8; ++it) {
        const int u = it * NT + tid;           // 0..2047
        const int row = u >> 4, q4 = u & 15;
        const int gr = (base + row < n) ? (base + row) : (n - 1);
        const float4 v = ((const float4*)(x + (size_t)gr * D_IN))[q4];

        __half2 h0 = __float22half2_rn(make_float2(v.x, v.y));
        __half2 h1 = __float22half2_rn(make_float2(v.z, v.w));
        uint2 hv;
        hv.x = *reinterpret_cast<uint32_t*>(&h0);
        hv.y = *reinterpret_cast<uint32_t*>(&h1);
        *(uint2*)(smem + SM_XH + row * 144 + q4 * 8) = hv;
    }
    __syncthreads();

    // ---- HMMA mainloop: warp owns rows [16*wid, 16*wid+16) ----
    float acc[32];                             // 8 n-tiles x {d0,d1,d2,d3}
    #pragma unroll
    for (int i = 0; i < 32; ++i) acc[i] = 0.f;

    const int rowA  = wid * 16 + g;            // A row for a0/a2
    const uint32_t aoff = (uint32_t)(rowA * 144 + 4 * t);
    const uint32_t boff = (uint32_t)(g * 144 + 4 * t);

    #pragma unroll
    for (int ks = 0; ks < 4; ++ks) {
        const uint32_t ak = aoff + ks * 32;
        const uint32_t a0 = *(const uint32_t*)(smem + SM_XH + ak);
        const uint32_t a1 = *(const uint32_t*)(smem + SM_XH + ak + 8 * 144);
        const uint32_t a2 = *(const uint32_t*)(smem + SM_XH + ak + 16);
        const uint32_t a3 = *(const uint32_t*)(smem + SM_XH + ak + 8 * 144 + 16);

        #pragma unroll
        for (int nt = 0; nt < 8; ++nt) {
            const uint32_t bk = boff + nt * 8 * 144 + ks * 32;
            const uint32_t bh0 = *(const uint32_t*)(smem + SM_WH + bk);
            const uint32_t bh1 = *(const uint32_t*)(smem + SM_WH + bk + 16);
            const uint32_t bl0 = *(const uint32_t*)(smem + SM_WL + bk);
            const uint32_t bl1 = *(const uint32_t*)(smem + SM_WL + bk + 16);
            float* a = acc + nt * 4;
            mma_f16(a[0], a[1], a[2], a[3], a0, a1, a2, a3, bh0, bh1);
            mma_f16(a[0], a[1], a[2], a[3], a0, a1, a2, a3, bl0, bl1);
        }
    }

    // ---- Direct-from-fragment epilogue ----
    {
        const float* sc = (const float*)(smem + SM_SC);
        const float* bw = (const float*)(smem + SM_BW);
        const float* bb = (const float*)(smem + SM_B2);
        const int r0 = wid * 16 + g;
        const int node0 = base + r0;
        const int node1 = node0 + 8;
        const bool v0 = (node0 < n);
        const bool v1 = (node1 < n);
        const float s0 = sc[r0];
        const float s1 = sc[r0 + 8];
        float* op0 = out + (size_t)node0 * D_OUT;
        float* op1 = out + (size_t)node1 * D_OUT;

        #pragma unroll
        for (int nt = 0; nt < 8; ++nt) {
            const int c = nt * 8 + 2 * t;
            const float2 bwv = *(const float2*)(bw + c);
            const float2 bbv = *(const float2*)(bb + c);
            const float* a = acc + nt * 4;
            if (v0) {
                float2 r;
                r.x = fmaf(s0, a[0] + bwv.x, bbv.x);
                r.y = fmaf(s0, a[1] + bwv.y, bbv.y);
                *(float2*)(op0 + c) = r;
            }
            if (v1) {
                float2 r;
                r.x = fmaf(s1, a[2] + bwv.x, bbv.x);
                r.y = fmaf(s1, a[3] + bwv.y, bbv.y);
                *(float2*)(op1 + c) = r;
            }
        }
    }
}

// ---------------------------------------------------------------------------
extern "C" void kernel_launch(void* const* d_in, const int* in_sizes, int n_in,
                              void* d_out, int out_size) {
    const float* x  = (const float*)d_in[0];
    const void*  ei = d_in[1];
    const float* W1 = (const float*)d_in[2];
    const float* b1 = (const float*)d_in[3];
    const float* W2 = (const float*)d_in[4];
    const float* b2 = (const float*)d_in[5];
    float* out = (float*)d_out;

    const int n = in_sizes[0] / D_IN;   // 100000
    const int E = in_sizes[1] / 2;      // 1000000

    const int hist_blocks = (E + 256 * EPT - 1) / (256 * EPT);
    prep_hist_kernel<<<PREP_BLOCKS + hist_blocks, 256>>>(
        (const int*)ei, W1, b1, W2, E);

    cudaFuncSetAttribute(gnn_mma_kernel,
                         cudaFuncAttributeMaxDynamicSharedMemorySize, SM_TOTAL);
    gnn_mma_kernel<<<(n + NPB - 1) / NPB, NT, SM_TOTAL>>>(x, b2, out, n);
}

// round 14
// speedup vs baseline: 1.1792x; 1.1000x over previous
#include <cuda_runtime.h>
#include <cuda_fp16.h>
#include <cstdint>

#define D_IN   64
#define D_OUT  64
#define D_HID  128
#define MAX_NODES 100000
#define NPB    128                 // nodes per block (M tile)
#define NT     256                 // threads per block (8 warps x 16 rows)
#define PREP_BLOCKS 65
#define EPT    8

// Scratch. g_deg: consume-reset invariant (zero at load, reset after read).
__device__ int   g_deg[MAX_NODES];
__device__ float g_bW[D_OUT];
// W12^T row-major [c][k], single fp16 (k contiguous).
__device__ __align__(16) unsigned short g_WT_h[D_OUT * D_IN];

// ---------------------------------------------------------------------------
__device__ __forceinline__ void mma_f16(float& d0, float& d1, float& d2, float& d3,
                                        uint32_t a0, uint32_t a1, uint32_t a2, uint32_t a3,
                                        uint32_t b0, uint32_t b1) {
    asm volatile(
        "mma.sync.aligned.m16n8k16.row.col.f32.f16.f16.f32 "
        "{%0,%1,%2,%3}, {%4,%5,%6,%7}, {%8,%9}, {%0,%1,%2,%3};"
        : "+f"(d0), "+f"(d1), "+f"(d2), "+f"(d3)
        : "r"(a0), "r"(a1), "r"(a2), "r"(a3), "r"(b0), "r"(b1));
}

// ---------------------------------------------------------------------------
// K1: blocks [0,65) -> W12^T fp16 + bW. Rest: degree histogram.
__global__ __launch_bounds__(256) void prep_hist_kernel(
    const int* __restrict__ ei32,
    const float* __restrict__ W1,
    const float* __restrict__ b1,
    const float* __restrict__ W2,
    int E)
{
    const int tid = threadIdx.x;

    if (blockIdx.x < PREP_BLOCKS) {
        const int r  = blockIdx.x;       // k index (or 64 => bW)
        const int j  = tid & 63;         // output column c
        const int kc = tid >> 6;
        const float* src = (r < D_IN) ? (W1 + (size_t)r * D_HID) : b1;

        float a = 0.f;
        #pragma unroll 8
        for (int k = kc * 32; k < kc * 32 + 32; ++k)
            a = fmaf(src[k], W2[(size_t)k * D_OUT + j], a);

        __shared__ float red[4][64];
        red[kc][j] = a;
        __syncthreads();
        if (kc == 0) {
            float v = red[0][j] + red[1][j] + red[2][j] + red[3][j];
            if (r < D_IN) {
                __half h = __float2half_rn(v);
                g_WT_h[j * D_IN + r] = *reinterpret_cast<unsigned short*>(&h);
            } else {
                g_bW[j] = v;
            }
        }
        return;
    }

    // ---- histogram over edge_index[1] (dst row), dtype self-detecting ----
    __shared__ int s_is64;
    if (tid == 0) {
        int is64 = 1;
        #pragma unroll
        for (int i = 1; i < 64; i += 2)
            if (ei32[i] != 0) is64 = 0;
        s_is64 = is64;
    }
    __syncthreads();

    const int hb = blockIdx.x - PREP_BLOCKS;
    const long long i0 = ((long long)hb * 256 + tid) * EPT;
    if (i0 >= E) return;

    if (s_is64) {
        const unsigned long long* p = (const unsigned long long*)ei32 + E;
        if (i0 + EPT <= E) {
            const ulonglong2* q = (const ulonglong2*)(p + i0);
            #pragma unroll
            for (int c = 0; c < EPT / 2; ++c) {
                ulonglong2 v = q[c];
                atomicAdd(&g_deg[(int)v.x], 1);
                atomicAdd(&g_deg[(int)v.y], 1);
            }
        } else {
            for (long long j = i0; j < E; ++j) atomicAdd(&g_deg[(int)p[j]], 1);
        }
    } else {
        const int* p = (const int*)ei32 + E;
        if (i0 + EPT <= E) {
            const int4* q = (const int4*)(p + i0);
            #pragma unroll
            for (int c = 0; c < EPT / 4; ++c) {
                int4 v = q[c];
                atomicAdd(&g_deg[v.x], 1); atomicAdd(&g_deg[v.y], 1);
                atomicAdd(&g_deg[v.z], 1); atomicAdd(&g_deg[v.w], 1);
            }
        } else {
            for (long long j = i0; j < E; ++j) atomicAdd(&g_deg[p[j]], 1);
        }
    }
}

// ---------------------------------------------------------------------------
// SMEM byte offsets (dynamic)
#define SM_SC  0                              // 128 f32 scales (1+deg)
#define SM_BW  512                            // 64 f32
#define SM_B2  768                            // 64 f32
#define SM_WH  1024                           // 64 x 144B
#define SM_XH  (SM_WH + 64 * 144)             // 128 x 144B (fp16)
#define SM_TOTAL (SM_XH + 128 * 144)          // 28672 B

// K2 (HMMA fp16): per block of 128 nodes,
//   D = x_h @ W_h  (both single fp16, fp32 acc)
//   out[n] = (1+deg)*(D[n] + bW) + b2 — stored straight from fragments.
__global__ __launch_bounds__(NT, 4) void gnn_mma_kernel(
    const float* __restrict__ x,
    const float* __restrict__ b2,
    float* __restrict__ out,
    int n)
{
    extern __shared__ char smem[];
    const int tid = threadIdx.x;
    const int wid = tid >> 5;
    const int lid = tid & 31;
    const int g   = lid >> 2;                  // 0..7
    const int t   = lid & 3;                   // 0..3
    const int base = blockIdx.x * NPB;

    // Degree read + consume-reset + scale into smem
    if (tid < NPB) {
        const int node = base + tid;
        int d = 0;
        if (node < n) { d = g_deg[node]; g_deg[node] = 0; }
        ((float*)(smem + SM_SC))[tid] = 1.0f + (float)d;
    }
    if (tid < D_OUT) {
        ((float*)(smem + SM_BW))[tid] = g_bW[tid];
        ((float*)(smem + SM_B2))[tid] = b2[tid];
    }

    // Stage W^T: 64 rows x 64 fp16 (=16 uint2/row) -> padded rows
    #pragma unroll
    for (int it = 0; it < 4; ++it) {
        const int u = it * NT + tid;           // 0..1023
        const int c = u >> 4, q = u & 15;
        *(uint2*)(smem + SM_WH + c * 144 + q * 8) =
            *(const uint2*)((const char*)g_WT_h + c * 128 + q * 8);
    }

    // Stage x: f32 -> fp16 (single), padded rows
    #pragma unroll
    for (int it = 0; it < 8; ++it) {
        const int u = it * NT + tid;           // 0..2047
        const int row = u >> 4, q4 = u & 15;
        const int gr = (base + row < n) ? (base + row) : (n - 1);
        const float4 v = ((const float4*)(x + (size_t)gr * D_IN))[q4];

        __half2 h0 = __float22half2_rn(make_float2(v.x, v.y));
        __half2 h1 = __float22half2_rn(make_float2(v.z, v.w));
        uint2 hv;
        hv.x = *reinterpret_cast<uint32_t*>(&h0);
        hv.y = *reinterpret_cast<uint32_t*>(&h1);
        *(uint2*)(smem + SM_XH + row * 144 + q4 * 8) = hv;
    }
    __syncthreads();

    // ---- HMMA mainloop: warp owns rows [16*wid, 16*wid+16) ----
    float acc[32];                             // 8 n-tiles x {d0,d1,d2,d3}
    #pragma unroll
    for (int i = 0; i < 32; ++i) acc[i] = 0.f;

    const int rowA  = wid * 16 + g;            // A row for a0/a2
    const uint32_t aoff = (uint32_t)(rowA * 144 + 4 * t);
    const uint32_t boff = (uint32_t)(g * 144 + 4 * t);

    #pragma unroll
    for (int ks = 0; ks < 4; ++ks) {
        const uint32_t ak = aoff + ks * 32;
        const uint32_t a0 = *(const uint32_t*)(smem + SM_XH + ak);
        const uint32_t a1 = *(const uint32_t*)(smem + SM_XH + ak + 8 * 144);
        const uint32_t a2 = *(const uint32_t*)(smem + SM_XH + ak + 16);
        const uint32_t a3 = *(const uint32_t*)(smem + SM_XH + ak + 8 * 144 + 16);

        #pragma unroll
        for (int nt = 0; nt < 8; ++nt) {
            const uint32_t bk = boff + nt * 8 * 144 + ks * 32;
            const uint32_t b0 = *(const uint32_t*)(smem + SM_WH + bk);
            const uint32_t b1 = *(const uint32_t*)(smem + SM_WH + bk + 16);
            float* a = acc + nt * 4;
            mma_f16(a[0], a[1], a[2], a[3], a0, a1, a2, a3, b0, b1);
        }
    }

    // ---- Direct-from-fragment epilogue ----
    {
        const float* sc = (const float*)(smem + SM_SC);
        const float* bw = (const float*)(smem + SM_BW);
        const float* bb = (const float*)(smem + SM_B2);
        const int r0 = wid * 16 + g;
        const int node0 = base + r0;
        const int node1 = node0 + 8;
        const bool v0 = (node0 < n);
        const bool v1 = (node1 < n);
        const float s0 = sc[r0];
        const float s1 = sc[r0 + 8];
        float* op0 = out + (size_t)node0 * D_OUT;
        float* op1 = out + (size_t)node1 * D_OUT;

        #pragma unroll
        for (int nt = 0; nt < 8; ++nt) {
            const int c = nt * 8 + 2 * t;
            const float2 bwv = *(const float2*)(bw + c);
            const float2 bbv = *(const float2*)(bb + c);
            const float* a = acc + nt * 4;
            if (v0) {
                float2 r;
                r.x = fmaf(s0, a[0] + bwv.x, bbv.x);
                r.y = fmaf(s0, a[1] + bwv.y, bbv.y);
                *(float2*)(op0 + c) = r;
            }
            if (v1) {
                float2 r;
                r.x = fmaf(s1, a[2] + bwv.x, bbv.x);
                r.y = fmaf(s1, a[3] + bwv.y, bbv.y);
                *(float2*)(op1 + c) = r;
            }
        }
    }
}

// ---------------------------------------------------------------------------
extern "C" void kernel_launch(void* const* d_in, const int* in_sizes, int n_in,
                              void* d_out, int out_size) {
    const float* x  = (const float*)d_in[0];
    const void*  ei = d_in[1];
    const float* W1 = (const float*)d_in[2];
    const float* b1 = (const float*)d_in[3];
    const float* W2 = (const float*)d_in[4];
    const float* b2 = (const float*)d_in[5];
    float* out = (float*)d_out;

    const int n = in_sizes[0] / D_IN;   // 100000
    const int E = in_sizes[1] / 2;      // 1000000

    const int hist_blocks = (E + 256 * EPT - 1) / (256 * EPT);
    prep_hist_kernel<<<PREP_BLOCKS + hist_blocks, 256>>>(
        (const int*)ei, W1, b1, W2, E);

    cudaFuncSetAttribute(gnn_mma_kernel,
                         cudaFuncAttributeMaxDynamicSharedMemorySize, SM_TOTAL);
    gnn_mma_kernel<<<(n + NPB - 1) / NPB, NT, SM_TOTAL>>>(x, b2, out, n);
}